// round 11
// baseline (speedup 1.0000x reference)
#include <cuda_runtime.h>
#include <cstdint>

#define DEV __device__ __forceinline__

// ---------------- problem constants ----------------
static constexpr int T_TOK = 8192;          // B*S = 4*2048
static constexpr int HID   = 1024;
static constexpr int FFND  = 4096;
static constexpr int NE    = 8;
static constexpr int ROWS_PAD = 17408;      // 16384 + 8*128 pad = 136*128

// ---------------- device scratch (bss, no runtime allocations) ----------------
__device__ float g_hmid[(size_t)ROWS_PAD * FFND];   // permuted fc1 output
__device__ float g_out2[(size_t)ROWS_PAD * HID];    // per-slot fc2 contribution
__device__ int   g_perm_token[ROWS_PAD];            // padded rows = -1
__device__ int   g_pos[T_TOK * 2];
__device__ int   g_topk_idx[T_TOK * 2];
__device__ float g_topk_w[T_TOK * 2];
__device__ int   g_counts[NE];
__device__ int   g_fill[NE];
__device__ int   g_offp[NE + 1];

// ---------------- PTX helpers ----------------
DEV uint32_t smem_u32(const void* p) {
    uint32_t a;
    asm("{ .reg .u64 t; cvta.to.shared.u64 t, %1; cvt.u32.u64 %0, t; }" : "=r"(a) : "l"(p));
    return a;
}
DEV uint32_t tf32(float f) {
    uint32_t r;
    asm("cvt.rna.tf32.f32 %0, %1;" : "=r"(r) : "f"(f));
    return r;
}
DEV void cpa16(uint32_t dst, const void* src, bool v) {
    int sz = v ? 16 : 0;
    asm volatile("cp.async.cg.shared.global [%0], [%1], 16, %2;"
                 :: "r"(dst), "l"(src), "r"(sz) : "memory");
}
DEV void cp_commit() { asm volatile("cp.async.commit_group;" ::: "memory"); }

DEV void mma8(float* c, const uint32_t* a, const uint32_t* b) {
    asm volatile(
        "mma.sync.aligned.m16n8k8.row.col.f32.tf32.tf32.f32 "
        "{%0,%1,%2,%3}, {%4,%5,%6,%7}, {%8,%9}, {%0,%1,%2,%3};"
        : "+f"(c[0]), "+f"(c[1]), "+f"(c[2]), "+f"(c[3])
        : "r"(a[0]), "r"(a[1]), "r"(a[2]), "r"(a[3]), "r"(b[0]), "r"(b[1]));
}

// swizzled smem float index inside a (rows x 32) K-major tile
DEV int sidx(int row, int k) {
    return row * 32 + ((((k >> 2) ^ (row & 7))) << 2) + (k & 3);
}
DEV float silu(float x) { return x / (1.0f + expf(-x)); }

// ---------------- small kernels ----------------
__global__ void k_init() {
    int i = blockIdx.x * 256 + threadIdx.x;
    if (i < ROWS_PAD) g_perm_token[i] = -1;
    if (i < NE) { g_counts[i] = 0; g_fill[i] = 0; }
}

__global__ __launch_bounds__(256) void k_router(const float* __restrict__ x,
                                                const float* __restrict__ Wr) {
    __shared__ float wr[NE * HID];  // 32 KB
    int tid = threadIdx.x;
    for (int i = tid; i < NE * HID; i += 256) wr[i] = Wr[i];
    __syncthreads();
    int warp = tid >> 5, lane = tid & 31;
    int t = blockIdx.x * 8 + warp;
    const float* xr = x + (size_t)t * HID;
    float acc[NE];
#pragma unroll
    for (int e = 0; e < NE; e++) acc[e] = 0.f;
    for (int i = lane; i < HID; i += 32) {
        float xv = xr[i];
#pragma unroll
        for (int e = 0; e < NE; e++) acc[e] = fmaf(xv, wr[e * HID + i], acc[e]);
    }
#pragma unroll
    for (int e = 0; e < NE; e++)
#pragma unroll
        for (int o = 16; o > 0; o >>= 1) acc[e] += __shfl_xor_sync(0xFFFFFFFFu, acc[e], o);
    if (lane == 0) {
        float m = acc[0];
#pragma unroll
        for (int e = 1; e < NE; e++) m = fmaxf(m, acc[e]);
        float p[NE], s = 0.f;
#pragma unroll
        for (int e = 0; e < NE; e++) { p[e] = expf(acc[e] - m); s += p[e]; }
        float inv = 1.f / s;
#pragma unroll
        for (int e = 0; e < NE; e++) p[e] *= inv;
        int e0 = 0;
#pragma unroll
        for (int e = 1; e < NE; e++) if (p[e] > p[e0]) e0 = e;
        int e1 = (e0 == 0) ? 1 : 0;
#pragma unroll
        for (int e = 0; e < NE; e++) if (e != e0 && p[e] > p[e1]) e1 = e;
        g_topk_idx[2 * t] = e0;    g_topk_idx[2 * t + 1] = e1;
        g_topk_w[2 * t]   = p[e0]; g_topk_w[2 * t + 1]   = p[e1];
        atomicAdd(&g_counts[e0], 1);
        atomicAdd(&g_counts[e1], 1);
    }
}

__global__ void k_offsets() {
    if (threadIdx.x == 0 && blockIdx.x == 0) {
        int a = 0;
        for (int e = 0; e < NE; e++) {
            g_offp[e] = a;
            a += ((g_counts[e] + 127) >> 7) << 7;
        }
        g_offp[NE] = a;
    }
}

__global__ void k_scatter() {
    int t = blockIdx.x * 256 + threadIdx.x;
    if (t >= T_TOK) return;
#pragma unroll
    for (int s = 0; s < 2; s++) {
        int e = g_topk_idx[2 * t + s];
        int pos = g_offp[e] + atomicAdd(&g_fill[e], 1);
        g_perm_token[pos] = t;
        g_pos[2 * t + s] = pos;
    }
}

__global__ void k_combine(float* __restrict__ out) {
    int t = blockIdx.x;
    int c = threadIdx.x * 4;
    float w0 = g_topk_w[2 * t], w1 = g_topk_w[2 * t + 1];
    int p0 = g_pos[2 * t], p1 = g_pos[2 * t + 1];
    float4 a = *(const float4*)&g_out2[(size_t)p0 * HID + c];
    float4 b = *(const float4*)&g_out2[(size_t)p1 * HID + c];
    float4 o;
    o.x = w0 * a.x + w1 * b.x;
    o.y = w0 * a.y + w1 * b.y;
    o.z = w0 * a.z + w1 * b.z;
    o.w = w0 * a.w + w1 * b.w;
    *(float4*)&out[(size_t)t * HID + c] = o;
}

// ---------------- grouped GEMM (tf32 mma.sync), tile 128x256 ----------------
// FC1: hmid = silu(X[perm] @ W1[e]^T + b1[e])   K=1024
// FC2: out2 =       hmid   @ W2[e]^T + b2[e]    K=4096
// 8 warps (2x4), warp tile 64x64. BK=32. 3-stage cp.async pipeline with a
// single __syncthreads per chunk:
//   wait_group(1); sync; load chunk i+2 -> stage (i+2)%3; compute stage i%3.

template <bool FC1>
__global__ __launch_bounds__(256, 1) void k_gemm(const float* __restrict__ Ain_,
                                                 const float* __restrict__ W,
                                                 const float* __restrict__ bias) {
    constexpr int K  = FC1 ? HID : FFND;
    constexpr int NT = FC1 ? FFND : HID;
    constexpr int KT = K / 32;
    constexpr uint32_t STAGE = 49152;            // 16 KB A + 32 KB B

    extern __shared__ float dsm[];
    __shared__ int s_tok[128];

    const int tid = threadIdx.x;
    const int wid = tid >> 5, lane = tid & 31;
    const int rbase = blockIdx.y * 128;
    const int nbase = blockIdx.x * 256;

    int e = 0;
    while (e < NE - 1 && rbase >= g_offp[e + 1]) e++;
    const float* Wexp = W + (size_t)e * NT * K;
    const float* Bias = bias + (size_t)e * NT;

    if (FC1 && tid < 128) s_tok[tid] = g_perm_token[rbase + tid];
    __syncthreads();

    const uint32_t sb = (smem_u32(dsm) + 1023) & ~1023u;   // align for swizzle
    const int lrow = tid >> 3, u = tid & 7;
    const uint32_t dA0 = sb + lrow * 128 + ((u ^ (lrow & 7)) << 4);
    const uint32_t dB0 = sb + 16384 + lrow * 128 + ((u ^ (lrow & 7)) << 4);

    // A sources (4 x 16B per stage), B sources (8 x 16B per stage)
    const float* srcA[4]; bool vA[4];
#pragma unroll
    for (int i = 0; i < 4; i++) {
        int row = i * 32 + lrow;
        if (FC1) {
            int tok = s_tok[row];
            vA[i] = (tok >= 0);
            srcA[i] = Ain_ + (size_t)(tok < 0 ? 0 : tok) * K + u * 4;
        } else {
            vA[i] = true;
            srcA[i] = g_hmid + (size_t)(rbase + row) * K + u * 4;
        }
    }
    const float* srcB0 = Wexp + (size_t)(nbase + lrow) * K + u * 4;

    auto load_stage = [&](int s, int chunk) {
        uint32_t boff = (uint32_t)s * STAGE;
        int koff = chunk * 32;
#pragma unroll
        for (int i = 0; i < 4; i++)
            cpa16(dA0 + boff + i * 4096u, srcA[i] + koff, vA[i]);
#pragma unroll
        for (int i = 0; i < 8; i++)
            cpa16(dB0 + boff + i * 4096u, srcB0 + (size_t)i * 32 * K + koff, true);
        cp_commit();
    };

    float acc[4][8][4];
#pragma unroll
    for (int mi = 0; mi < 4; mi++)
#pragma unroll
        for (int ni = 0; ni < 8; ni++)
#pragma unroll
            for (int c = 0; c < 4; c++) acc[mi][ni][c] = 0.f;

    const int wm = (wid >> 2) * 64;        // 0 or 64 within 128 rows
    const int wn = (wid & 3) * 64;         // 0..192 within 256 cols

    load_stage(0, 0);
    load_stage(1, 1);

    for (int i = 0; i < KT; i++) {
        if (i == KT - 1) asm volatile("cp.async.wait_group 0;" ::: "memory");
        else             asm volatile("cp.async.wait_group 1;" ::: "memory");
        __syncthreads();
        if (i + 2 < KT) load_stage((i + 2) % 3, i + 2);

        const float* sA = dsm + ((sb - smem_u32(dsm)) >> 2) + (i % 3) * (STAGE >> 2);
        const float* sB = sA + 4096;
#pragma unroll
        for (int kk = 0; kk < 4; kk++) {
            int k0 = kk * 8 + (lane & 3);
            uint32_t af[4][4], bf[8][2];
#pragma unroll
            for (int mi = 0; mi < 4; mi++) {
                int r0 = wm + mi * 16 + (lane >> 2);
                af[mi][0] = tf32(sA[sidx(r0,     k0)]);
                af[mi][1] = tf32(sA[sidx(r0 + 8, k0)]);
                af[mi][2] = tf32(sA[sidx(r0,     k0 + 4)]);
                af[mi][3] = tf32(sA[sidx(r0 + 8, k0 + 4)]);
            }
#pragma unroll
            for (int ni = 0; ni < 8; ni++) {
                int n0 = wn + ni * 8 + (lane >> 2);
                bf[ni][0] = tf32(sB[sidx(n0, k0)]);
                bf[ni][1] = tf32(sB[sidx(n0, k0 + 4)]);
            }
#pragma unroll
            for (int mi = 0; mi < 4; mi++)
#pragma unroll
                for (int ni = 0; ni < 8; ni++)
                    mma8(acc[mi][ni], af[mi], bf[ni]);
        }
    }

    // epilogue: bias (+ SiLU for FC1), direct stores (rows incl. padding are fine)
    float* Out = FC1 ? g_hmid : g_out2;
#pragma unroll
    for (int mi = 0; mi < 4; mi++) {
        int r0 = rbase + wm + mi * 16 + (lane >> 2);
#pragma unroll
        for (int ni = 0; ni < 8; ni++) {
            int c0 = nbase + wn + ni * 8 + (lane & 3) * 2;
            float b0 = __ldg(&Bias[c0]), b1v = __ldg(&Bias[c0 + 1]);
            float2 v0 = make_float2(acc[mi][ni][0] + b0, acc[mi][ni][1] + b1v);
            float2 v1 = make_float2(acc[mi][ni][2] + b0, acc[mi][ni][3] + b1v);
            if (FC1) {
                v0.x = silu(v0.x); v0.y = silu(v0.y);
                v1.x = silu(v1.x); v1.y = silu(v1.y);
            }
            *(float2*)&Out[(size_t)r0 * NT + c0]       = v0;
            *(float2*)&Out[(size_t)(r0 + 8) * NT + c0] = v1;
        }
    }
}

// ---------------- launch ----------------
extern "C" void kernel_launch(void* const* d_in, const int* in_sizes, int n_in,
                              void* d_out, int out_size) {
    const float* x  = (const float*)d_in[0];
    const float* Wr = (const float*)d_in[1];
    const float* W1 = (const float*)d_in[2];
    const float* b1 = (const float*)d_in[3];
    const float* W2 = (const float*)d_in[4];
    const float* b2 = (const float*)d_in[5];
    float* out = (float*)d_out;

    constexpr int SMEM = 3 * 49152 + 1024;   // 148480
    cudaFuncSetAttribute(k_gemm<true>,  cudaFuncAttributeMaxDynamicSharedMemorySize, SMEM);
    cudaFuncSetAttribute(k_gemm<false>, cudaFuncAttributeMaxDynamicSharedMemorySize, SMEM);

    k_init<<<(ROWS_PAD + 255) / 256, 256>>>();
    k_router<<<T_TOK / 8, 256>>>(x, Wr);
    k_offsets<<<1, 32>>>();
    k_scatter<<<T_TOK / 256, 256>>>();
    k_gemm<true><<<dim3(FFND / 256, ROWS_PAD / 128), 256, SMEM>>>(x, W1, b1);
    k_gemm<false><<<dim3(HID / 256, ROWS_PAD / 128), 256, SMEM>>>(nullptr, W2, b2);
    k_combine<<<T_TOK, 256>>>(out);
}

// round 14
// speedup vs baseline: 1.8354x; 1.8354x over previous
#include <cuda_runtime.h>
#include <cstdint>

#define DEV __device__ __forceinline__

// ---------------- problem constants ----------------
static constexpr int T_TOK = 8192;          // B*S = 4*2048
static constexpr int HID   = 1024;
static constexpr int FFND  = 4096;
static constexpr int NE    = 8;
static constexpr int ROWS_PAD = 17408;      // 16384 + 8*128 pad = 136*128

// ---------------- device scratch (bss, no runtime allocations) ----------------
__device__ float g_xr [(size_t)T_TOK * HID];        // tf32-rounded x
__device__ float g_w1r[(size_t)NE * FFND * HID];    // tf32-rounded W1
__device__ float g_w2r[(size_t)NE * HID * FFND];    // tf32-rounded W2
__device__ float g_hmid[(size_t)ROWS_PAD * FFND];   // permuted fc1 out (tf32-rounded)
__device__ float g_out2[(size_t)ROWS_PAD * HID];    // per-slot fc2 contribution
__device__ int   g_perm_token[ROWS_PAD];            // padded rows = -1
__device__ int   g_pos[T_TOK * 2];
__device__ int   g_topk_idx[T_TOK * 2];
__device__ float g_topk_w[T_TOK * 2];
__device__ int   g_counts[NE];
__device__ int   g_fill[NE];
__device__ int   g_offp[NE + 1];

// ---------------- PTX helpers ----------------
DEV uint32_t smem_u32(const void* p) {
    uint32_t a;
    asm("{ .reg .u64 t; cvta.to.shared.u64 t, %1; cvt.u32.u64 %0, t; }" : "=r"(a) : "l"(p));
    return a;
}
DEV uint32_t tf32(float f) {
    uint32_t r;
    asm("cvt.rna.tf32.f32 %0, %1;" : "=r"(r) : "f"(f));
    return r;
}
DEV void cpa16(uint32_t dst, const void* src, bool v) {
    int sz = v ? 16 : 0;
    asm volatile("cp.async.cg.shared.global [%0], [%1], 16, %2;"
                 :: "r"(dst), "l"(src), "r"(sz) : "memory");
}
DEV void cp_commit() { asm volatile("cp.async.commit_group;" ::: "memory"); }

DEV void mma8(float* c, const uint32_t* a, const uint32_t* b) {
    asm volatile(
        "mma.sync.aligned.m16n8k8.row.col.f32.tf32.tf32.f32 "
        "{%0,%1,%2,%3}, {%4,%5,%6,%7}, {%8,%9}, {%0,%1,%2,%3};"
        : "+f"(c[0]), "+f"(c[1]), "+f"(c[2]), "+f"(c[3])
        : "r"(a[0]), "r"(a[1]), "r"(a[2]), "r"(a[3]), "r"(b[0]), "r"(b[1]));
}

DEV uint32_t lds32(const float* p) {            // raw b32 shared load (no cvt)
    return __float_as_uint(*p);
}

// swizzled smem float index inside a (rows x 32) K-major tile
DEV int sidx(int row, int k) {
    return row * 32 + ((((k >> 2) ^ (row & 7))) << 2) + (k & 3);
}
DEV float silu(float x) { return x / (1.0f + expf(-x)); }

// ---------------- small kernels ----------------
__global__ void k_init() {
    int i = blockIdx.x * 256 + threadIdx.x;
    if (i < ROWS_PAD) g_perm_token[i] = -1;
    if (i < NE) { g_counts[i] = 0; g_fill[i] = 0; }
}

__global__ void k_round(const float* __restrict__ src, float* __restrict__ dst, int n4) {
    int i = blockIdx.x * 256 + threadIdx.x;
    if (i < n4) {
        float4 v = ((const float4*)src)[i];
        v.x = __uint_as_float(tf32(v.x));
        v.y = __uint_as_float(tf32(v.y));
        v.z = __uint_as_float(tf32(v.z));
        v.w = __uint_as_float(tf32(v.w));
        ((float4*)dst)[i] = v;
    }
}

__global__ __launch_bounds__(256) void k_router(const float* __restrict__ x,
                                                const float* __restrict__ Wr) {
    __shared__ float wr[NE * HID];  // 32 KB
    int tid = threadIdx.x;
    for (int i = tid; i < NE * HID; i += 256) wr[i] = Wr[i];
    __syncthreads();
    int warp = tid >> 5, lane = tid & 31;
    int t = blockIdx.x * 8 + warp;
    const float* xr = x + (size_t)t * HID;
    float acc[NE];
#pragma unroll
    for (int e = 0; e < NE; e++) acc[e] = 0.f;
    for (int i = lane; i < HID; i += 32) {
        float xv = xr[i];
#pragma unroll
        for (int e = 0; e < NE; e++) acc[e] = fmaf(xv, wr[e * HID + i], acc[e]);
    }
#pragma unroll
    for (int e = 0; e < NE; e++)
#pragma unroll
        for (int o = 16; o > 0; o >>= 1) acc[e] += __shfl_xor_sync(0xFFFFFFFFu, acc[e], o);
    if (lane == 0) {
        float m = acc[0];
#pragma unroll
        for (int e = 1; e < NE; e++) m = fmaxf(m, acc[e]);
        float p[NE], s = 0.f;
#pragma unroll
        for (int e = 0; e < NE; e++) { p[e] = expf(acc[e] - m); s += p[e]; }
        float inv = 1.f / s;
#pragma unroll
        for (int e = 0; e < NE; e++) p[e] *= inv;
        int e0 = 0;
#pragma unroll
        for (int e = 1; e < NE; e++) if (p[e] > p[e0]) e0 = e;
        int e1 = (e0 == 0) ? 1 : 0;
#pragma unroll
        for (int e = 0; e < NE; e++) if (e != e0 && p[e] > p[e1]) e1 = e;
        g_topk_idx[2 * t] = e0;    g_topk_idx[2 * t + 1] = e1;
        g_topk_w[2 * t]   = p[e0]; g_topk_w[2 * t + 1]   = p[e1];
        atomicAdd(&g_counts[e0], 1);
        atomicAdd(&g_counts[e1], 1);
    }
}

__global__ void k_offsets() {
    if (threadIdx.x == 0 && blockIdx.x == 0) {
        int a = 0;
        for (int e = 0; e < NE; e++) {
            g_offp[e] = a;
            a += ((g_counts[e] + 127) >> 7) << 7;
        }
        g_offp[NE] = a;
    }
}

__global__ void k_scatter() {
    int t = blockIdx.x * 256 + threadIdx.x;
    if (t >= T_TOK) return;
#pragma unroll
    for (int s = 0; s < 2; s++) {
        int e = g_topk_idx[2 * t + s];
        int pos = g_offp[e] + atomicAdd(&g_fill[e], 1);
        g_perm_token[pos] = t;
        g_pos[2 * t + s] = pos;
    }
}

__global__ void k_combine(float* __restrict__ out) {
    int t = blockIdx.x;
    int c = threadIdx.x * 4;
    float w0 = g_topk_w[2 * t], w1 = g_topk_w[2 * t + 1];
    int p0 = g_pos[2 * t], p1 = g_pos[2 * t + 1];
    float4 a = *(const float4*)&g_out2[(size_t)p0 * HID + c];
    float4 b = *(const float4*)&g_out2[(size_t)p1 * HID + c];
    float4 o;
    o.x = w0 * a.x + w1 * b.x;
    o.y = w0 * a.y + w1 * b.y;
    o.z = w0 * a.z + w1 * b.z;
    o.w = w0 * a.w + w1 * b.w;
    *(float4*)&out[(size_t)t * HID + c] = o;
}

// ---------------- grouped GEMM (tf32 mma.sync), tile 128x128 ----------------
// Operands pre-rounded to tf32 (fp32 bit layout) -> no cvt in the inner loop.
// 8 warps (2x4), warp tile 64x32. BK=32. 3-stage cp.async pipeline,
// one __syncthreads per chunk, 2 CTAs/SM.

template <bool FC1>
__global__ __launch_bounds__(256, 2) void k_gemm(const float* __restrict__ Ain_,
                                                 const float* __restrict__ W,
                                                 const float* __restrict__ bias) {
    constexpr int K  = FC1 ? HID : FFND;
    constexpr int NT = FC1 ? FFND : HID;
    constexpr int KT = K / 32;
    constexpr uint32_t STAGE = 32768;            // 16 KB A + 16 KB B

    extern __shared__ float dsm[];
    __shared__ int s_tok[128];

    const int tid = threadIdx.x;
    const int wid = tid >> 5, lane = tid & 31;
    const int rbase = blockIdx.y * 128;
    const int nbase = blockIdx.x * 128;

    int e = 0;
    while (e < NE - 1 && rbase >= g_offp[e + 1]) e++;
    const float* Wexp = W + (size_t)e * NT * K;
    const float* Bias = bias + (size_t)e * NT;

    if (FC1 && tid < 128) s_tok[tid] = g_perm_token[rbase + tid];
    __syncthreads();

    const uint32_t sb = (smem_u32(dsm) + 1023) & ~1023u;   // align for swizzle
    const int lrow = tid >> 3, u = tid & 7;
    const uint32_t dA0 = sb + lrow * 128 + ((u ^ (lrow & 7)) << 4);
    const uint32_t dB0 = sb + 16384 + lrow * 128 + ((u ^ (lrow & 7)) << 4);

    const float* srcA[4]; bool vA[4];
#pragma unroll
    for (int i = 0; i < 4; i++) {
        int row = i * 32 + lrow;
        if (FC1) {
            int tok = s_tok[row];
            vA[i] = (tok >= 0);
            srcA[i] = Ain_ + (size_t)(tok < 0 ? 0 : tok) * K + u * 4;
        } else {
            vA[i] = true;
            srcA[i] = g_hmid + (size_t)(rbase + row) * K + u * 4;
        }
    }
    const float* srcB0 = Wexp + (size_t)(nbase + lrow) * K + u * 4;

    auto load_stage = [&](int s, int chunk) {
        uint32_t boff = (uint32_t)s * STAGE;
        int koff = chunk * 32;
#pragma unroll
        for (int i = 0; i < 4; i++)
            cpa16(dA0 + boff + i * 4096u, srcA[i] + koff, vA[i]);
#pragma unroll
        for (int i = 0; i < 4; i++)
            cpa16(dB0 + boff + i * 4096u, srcB0 + (size_t)i * 32 * K + koff, true);
        cp_commit();
    };

    float acc[4][4][4];
#pragma unroll
    for (int mi = 0; mi < 4; mi++)
#pragma unroll
        for (int ni = 0; ni < 4; ni++)
#pragma unroll
            for (int c = 0; c < 4; c++) acc[mi][ni][c] = 0.f;

    const int wm = (wid >> 2) * 64;        // 0 or 64
    const int wn = (wid & 3) * 32;         // 0..96

    load_stage(0, 0);
    load_stage(1, 1);

    const float* sbf = dsm + ((sb - smem_u32(dsm)) >> 2);
    for (int i = 0; i < KT; i++) {
        if (i == KT - 1) asm volatile("cp.async.wait_group 0;" ::: "memory");
        else             asm volatile("cp.async.wait_group 1;" ::: "memory");
        __syncthreads();
        if (i + 2 < KT) load_stage((i + 2) % 3, i + 2);

        const float* sA = sbf + (i % 3) * (STAGE >> 2);
        const float* sB = sA + 4096;
#pragma unroll
        for (int kk = 0; kk < 4; kk++) {
            int k0 = kk * 8 + (lane & 3);
            uint32_t af[4][4], bf[4][2];
#pragma unroll
            for (int mi = 0; mi < 4; mi++) {
                int r0 = wm + mi * 16 + (lane >> 2);
                af[mi][0] = lds32(&sA[sidx(r0,     k0)]);
                af[mi][1] = lds32(&sA[sidx(r0 + 8, k0)]);
                af[mi][2] = lds32(&sA[sidx(r0,     k0 + 4)]);
                af[mi][3] = lds32(&sA[sidx(r0 + 8, k0 + 4)]);
            }
#pragma unroll
            for (int ni = 0; ni < 4; ni++) {
                int n0 = wn + ni * 8 + (lane >> 2);
                bf[ni][0] = lds32(&sB[sidx(n0, k0)]);
                bf[ni][1] = lds32(&sB[sidx(n0, k0 + 4)]);
            }
#pragma unroll
            for (int mi = 0; mi < 4; mi++)
#pragma unroll
                for (int ni = 0; ni < 4; ni++)
                    mma8(acc[mi][ni], af[mi], bf[ni]);
        }
    }

    // epilogue: bias (+ SiLU and tf32-round for FC1)
    float* Out = FC1 ? g_hmid : g_out2;
#pragma unroll
    for (int mi = 0; mi < 4; mi++) {
        int r0 = rbase + wm + mi * 16 + (lane >> 2);
#pragma unroll
        for (int ni = 0; ni < 4; ni++) {
            int c0 = nbase + wn + ni * 8 + (lane & 3) * 2;
            float b0 = __ldg(&Bias[c0]), b1v = __ldg(&Bias[c0 + 1]);
            float2 v0 = make_float2(acc[mi][ni][0] + b0, acc[mi][ni][1] + b1v);
            float2 v1 = make_float2(acc[mi][ni][2] + b0, acc[mi][ni][3] + b1v);
            if (FC1) {
                v0.x = __uint_as_float(tf32(silu(v0.x)));
                v0.y = __uint_as_float(tf32(silu(v0.y)));
                v1.x = __uint_as_float(tf32(silu(v1.x)));
                v1.y = __uint_as_float(tf32(silu(v1.y)));
            }
            *(float2*)&Out[(size_t)r0 * NT + c0]       = v0;
            *(float2*)&Out[(size_t)(r0 + 8) * NT + c0] = v1;
        }
    }
}

// ---------------- launch ----------------
extern "C" void kernel_launch(void* const* d_in, const int* in_sizes, int n_in,
                              void* d_out, int out_size) {
    const float* x  = (const float*)d_in[0];
    const float* Wr = (const float*)d_in[1];
    const float* W1 = (const float*)d_in[2];
    const float* b1 = (const float*)d_in[3];
    const float* W2 = (const float*)d_in[4];
    const float* b2 = (const float*)d_in[5];
    float* out = (float*)d_out;

    static float* p_xr  = nullptr;
    static float* p_w1r = nullptr;
    static float* p_w2r = nullptr;
    constexpr int SMEM = 3 * 32768 + 1024;   // 99328
    if (!p_xr) {
        cudaGetSymbolAddress((void**)&p_xr,  g_xr);
        cudaGetSymbolAddress((void**)&p_w1r, g_w1r);
        cudaGetSymbolAddress((void**)&p_w2r, g_w2r);
        cudaFuncSetAttribute(k_gemm<true>,  cudaFuncAttributeMaxDynamicSharedMemorySize, SMEM);
        cudaFuncSetAttribute(k_gemm<false>, cudaFuncAttributeMaxDynamicSharedMemorySize, SMEM);
    }

    k_init<<<(ROWS_PAD + 255) / 256, 256>>>();
    k_round<<<(T_TOK * HID / 4 + 255) / 256, 256>>>(x,  p_xr,  T_TOK * HID / 4);
    k_round<<<(NE * FFND * HID / 4 + 255) / 256, 256>>>(W1, p_w1r, NE * FFND * HID / 4);
    k_round<<<(NE * HID * FFND / 4 + 255) / 256, 256>>>(W2, p_w2r, NE * HID * FFND / 4);
    k_router<<<T_TOK / 8, 256>>>(x, Wr);
    k_offsets<<<1, 32>>>();
    k_scatter<<<T_TOK / 256, 256>>>();
    k_gemm<true><<<dim3(FFND / 128, ROWS_PAD / 128), 256, SMEM>>>(p_xr, p_w1r, b1);
    k_gemm<false><<<dim3(HID / 128, ROWS_PAD / 128), 256, SMEM>>>(nullptr, p_w2r, b2);
    k_combine<<<T_TOK, 256>>>(out);
}